// round 15
// baseline (speedup 1.0000x reference)
#include <cuda_runtime.h>
#include <cuda_fp16.h>
#include <math.h>
#include <stdint.h>

#define TOKENS 4096
#define DDIM   1024

// ---------------------------------------------------------------------------
// scratch (__device__ globals; no cudaMalloc allowed)
// fp16 tiles, 128 rows x 64 cols = 16KB, SW128-pre-swizzled
// x: 32 mb x 16 kt = 512 tiles;  W1: 8 nb x 16 kt = 128 tiles
// w23: 16 kt tiles of 32 rows x 64 cols (rows 0-15 = W2, 16-31 = W3), 4KB each
// ---------------------------------------------------------------------------
__device__ float g_s[TOKENS];
__device__ int   g_s_flag[32];
__device__ __align__(1024) uint4 g_xhi[512 * 1024];
__device__ __align__(1024) uint4 g_whi[128 * 1024];
__device__ __align__(1024) uint4 g_w23[16 * 256];

__device__ __forceinline__ float softplusf(float z) {
    if (z > 20.0f) return z;
    return log1pf(expf(z));
}

__device__ __forceinline__ uint32_t smem_u32(const void* p) {
    uint32_t a;
    asm("{ .reg .u64 t; cvta.to.shared.u64 t, %1; cvt.u32.u64 %0, t; }"
        : "=r"(a) : "l"(p));
    return a;
}

#define MBARRIER_INIT(addr, cnt) \
    asm volatile("mbarrier.init.shared.b64 [%0], %1;" :: "r"(addr), "r"(cnt) : "memory")
#define MBARRIER_EXPECT_TX(addr, bytes) \
    asm volatile("mbarrier.arrive.expect_tx.shared.b64 _, [%0], %1;" \
        :: "r"(addr), "r"(bytes) : "memory")
#define MBARRIER_ARRIVE(addr) \
    asm volatile("mbarrier.arrive.shared.b64 _, [%0];" :: "r"(addr) : "memory")

#define MBARRIER_WAIT_PARITY(addr, parity) do { \
    uint32_t _m = (addr); uint32_t _p = (parity); uint32_t _d; \
    asm volatile("{\n\t.reg .pred p;\n\t" \
        "mbarrier.try_wait.parity.acquire.cta.shared::cta.b64 p, [%1], %2;\n\t" \
        "selp.b32 %0, 1, 0, p;\n\t}" : "=r"(_d) : "r"(_m), "r"(_p) : "memory"); \
    if (!_d) { \
        asm volatile("{\n\t.reg .pred P1;\n\t" \
            "WL_%=:\n\t" \
            "mbarrier.try_wait.parity.acquire.cta.shared::cta.b64 P1, [%0], %1, 0x989680;\n\t" \
            "@P1 bra.uni WD_%=;\n\t" \
            "bra.uni WL_%=;\n\t" \
            "WD_%=:\n\t}" :: "r"(_m), "r"(_p) : "memory"); \
    } \
} while (0)

__device__ __forceinline__ void bulk_g2s(uint32_t dst, const void* src,
                                         uint32_t bytes, uint32_t mbar) {
    asm volatile(
        "cp.async.bulk.shared::cluster.global.mbarrier::complete_tx::bytes "
        "[%0], [%1], %2, [%3];"
        :: "r"(dst), "l"(src), "r"(bytes), "r"(mbar) : "memory");
}

__device__ __forceinline__ void ldsm_x4(uint32_t* r, uint32_t addr) {
    asm volatile("ldmatrix.sync.aligned.m8n8.x4.shared.b16 {%0,%1,%2,%3}, [%4];"
                 : "=r"(r[0]), "=r"(r[1]), "=r"(r[2]), "=r"(r[3]) : "r"(addr));
}
__device__ __forceinline__ void mma16816h(float* d, const uint32_t* a,
                                          const uint32_t* b) {
    asm volatile(
        "mma.sync.aligned.m16n8k16.row.col.f32.f16.f16.f32 "
        "{%0,%1,%2,%3}, {%4,%5,%6,%7}, {%8,%9}, {%0,%1,%2,%3};"
        : "+f"(d[0]), "+f"(d[1]), "+f"(d[2]), "+f"(d[3])
        : "r"(a[0]), "r"(a[1]), "r"(a[2]), "r"(a[3]), "r"(b[0]), "r"(b[1]));
}

// ---------------------------------------------------------------------------
// Kernel 0 (prep = convert only):
//  blocks 0..511   : downcast x to fp16 128x64 tiles (SW128-pre-swizzled)
//  blocks 512..639 : downcast W1 likewise
//  blocks 640..655 : downcast W2/W3 into 32x64 w23 tiles (block = kt)
//  block  655 also zeroes g_s_flag
// ---------------------------------------------------------------------------
__global__ __launch_bounds__(256) void prep_kernel(
    const float* __restrict__ X, const float* __restrict__ W,
    const float* __restrict__ W2, const float* __restrict__ W3)
{
    const int bid = blockIdx.x;
    const int tid = threadIdx.x;

    if (bid >= 640) {
        // ---- w23 tiles ----
        const int kt = bid - 640;
        if (bid == 655 && tid >= 224) {   // zero flags (32 threads)
            g_s_flag[tid - 224] = 0;
        }
        int row = tid >> 3, c8 = tid & 7;
        const float* src = (row < 16) ? &W2[(size_t)row * DDIM]
                                      : &W3[(size_t)(row - 16) * DDIM];
        const float* p = src + kt * 64 + c8 * 8;
        float4 v0 = *reinterpret_cast<const float4*>(p);
        float4 v1 = *reinterpret_cast<const float4*>(p + 4);
        float v[8] = {v0.x, v0.y, v0.z, v0.w, v1.x, v1.y, v1.z, v1.w};
        uint32_t ph[4];
        #pragma unroll
        for (int i = 0; i < 4; ++i) {
            __half h0 = __float2half_rn(v[2 * i]);
            __half h1 = __float2half_rn(v[2 * i + 1]);
            ph[i] = (uint32_t)__half_as_ushort(h0) |
                    ((uint32_t)__half_as_ushort(h1) << 16);
        }
        uint32_t off = (uint32_t)(row * 128 + c8 * 16);
        off ^= ((off >> 3) & 0x70);
        g_w23[kt * 256 + (off >> 4)] = make_uint4(ph[0], ph[1], ph[2], ph[3]);
        return;
    }

    // ---- x / W1 tiles ----
    const float* src;
    uint4* dhi;
    if (bid < 512) {
        int mb = bid >> 4, kb = bid & 15;
        src = X + (size_t)mb * 128 * DDIM + kb * 64;
        dhi = g_xhi + (size_t)bid * 1024;
    } else {
        int t = bid - 512;
        int nb = t >> 4, kb = t & 15;
        src = W + (size_t)nb * 128 * DDIM + kb * 64;
        dhi = g_whi + (size_t)t * 1024;
    }
    #pragma unroll
    for (int it = 0; it < 4; ++it) {
        int c = tid + it * 256;
        int row = c >> 3, c8 = c & 7;
        const float* p = src + (size_t)row * DDIM + c8 * 8;
        float4 v0 = *reinterpret_cast<const float4*>(p);
        float4 v1 = *reinterpret_cast<const float4*>(p + 4);
        float v[8] = {v0.x, v0.y, v0.z, v0.w, v1.x, v1.y, v1.z, v1.w};
        uint32_t ph[4];
        #pragma unroll
        for (int i = 0; i < 4; ++i) {
            __half h0 = __float2half_rn(v[2 * i]);
            __half h1 = __float2half_rn(v[2 * i + 1]);
            ph[i] = (uint32_t)__half_as_ushort(h0) |
                    ((uint32_t)__half_as_ushort(h1) << 16);
        }
        uint32_t off = (uint32_t)(row * 128 + c8 * 16);
        off ^= ((off >> 3) & 0x70);   // SW128 swizzle, pre-applied
        dhi[off >> 4] = make_uint4(ph[0], ph[1], ph[2], ph[3]);
    }
}

// ---------------------------------------------------------------------------
// Kernel 1: fused GEMM + s computation, 2 CTAs/SM.
// grid (9, 32): blockIdx.x == 0 -> s-CTA for row-block mb; else GEMM CTA.
// CTA = 288 threads: warps 0-7 compute (32x64 tiles), warp 8 = producer.
// BM=BN=128, BK=64, 3-stage bulk pipeline (32KB/stage, 96KB total -> 2 CTA/SM).
// ---------------------------------------------------------------------------
#define NKT 16                    // 1024 / 64
#define STAGES 3
#define PART_B 16384              // one 128x64 fp16 tile
#define STAGE_B (2 * PART_B)      // 32KB
#define GEMM_SMEM (STAGES * STAGE_B)   // 98304
#define S_STAGE_TX (16384 + 4096)

__global__ __launch_bounds__(288, 2) void gemm_kernel(
    const float* __restrict__ x,
    const float* __restrict__ b1,
    const float* __restrict__ b2,
    const float* __restrict__ b3,
    float* __restrict__ y)
{
    extern __shared__ __align__(1024) char smem[];
    __shared__ __align__(8) uint64_t mbar[2 * STAGES];

    const uint32_t sdyn = smem_u32(smem);
    const uint32_t sFull  = smem_u32(&mbar[0]);
    const uint32_t sEmpty = smem_u32(&mbar[STAGES]);

    const int tid  = threadIdx.x;
    const int wid  = tid >> 5;
    const int lane = tid & 31;
    const int nbx = blockIdx.x;         // 0 = s-CTA, 1..8 = GEMM
    const int mb  = blockIdx.y;         // 0..31
    const int rbase = mb * 128;
    const bool is_s = (nbx == 0);

    if (tid == 0) {
        #pragma unroll
        for (int s = 0; s < STAGES; ++s) {
            MBARRIER_INIT(sFull  + s * 8, 1);
            MBARRIER_INIT(sEmpty + s * 8, 8);
        }
    }
    __syncthreads();

    if (is_s) {
        // ==================== s-CTA ====================
        if (wid == 8) {
            if (lane == 0) {
                const char* xhiB = (const char*)g_xhi;
                const char* w23B = (const char*)g_w23;
                int st = 0, ph = 1;
                for (int kt = 0; kt < NKT; ++kt) {
                    MBARRIER_WAIT_PARITY(sEmpty + st * 8, ph);
                    uint32_t fb = sFull + st * 8;
                    MBARRIER_EXPECT_TX(fb, S_STAGE_TX);
                    uint32_t sb = sdyn + st * STAGE_B;
                    bulk_g2s(sb, xhiB + ((size_t)(mb * NKT + kt)) * PART_B,
                             PART_B, fb);
                    bulk_g2s(sb + PART_B, w23B + (size_t)kt * 4096, 4096, fb);
                    if (++st == STAGES) { st = 0; ph ^= 1; }
                }
            }
            return;
        }

        float acc[4][4];
        #pragma unroll
        for (int j = 0; j < 4; ++j)
            #pragma unroll
            for (int e = 0; e < 4; ++e)
                acc[j][e] = 0.f;

        const uint32_t aRow = (uint32_t)(wid * 16 + (lane & 15)) * 128;
        const uint32_t aSw  = (uint32_t)((wid * 16 + (lane & 15)) & 7);
        uint32_t bRow[2], bSw[2];
        #pragma unroll
        for (int jj = 0; jj < 2; ++jj) {
            int r = jj * 16 + (lane & 7) + ((lane >> 4) & 1) * 8;
            bRow[jj] = (uint32_t)r * 128;
            bSw[jj]  = (uint32_t)(r & 7);
        }
        const uint32_t ac0 = (uint32_t)(lane >> 4);
        const uint32_t bc0 = (uint32_t)((lane >> 3) & 1);

        int st = 0, ph = 0;
        for (int kt = 0; kt < NKT; ++kt) {
            MBARRIER_WAIT_PARITY(sFull + st * 8, ph);
            const uint32_t ah = sdyn + st * STAGE_B;
            const uint32_t bh = ah + PART_B;
            #pragma unroll
            for (int kk = 0; kk < 4; ++kk) {
                uint32_t Ah[4], Bf[2][4];
                const uint32_t ca = kk * 2 + ac0;
                const uint32_t cb = kk * 2 + bc0;
                ldsm_x4(Ah, ah + aRow + ((ca ^ aSw) << 4));
                #pragma unroll
                for (int jj = 0; jj < 2; ++jj)
                    ldsm_x4(Bf[jj], bh + bRow[jj] + ((cb ^ bSw[jj]) << 4));
                #pragma unroll
                for (int j = 0; j < 4; ++j)
                    mma16816h(acc[j], Ah, &Bf[j >> 1][(j & 1) * 2]);
            }
            if (lane == 0) MBARRIER_ARRIVE(sEmpty + st * 8);
            if (++st == STAGES) { st = 0; ph ^= 1; }
        }

        // s = sum_n (Bm + b2)(Cm + b3); cols 0-15 = Bm, 16-31 = Cm
        float s0 = 0.f, s1 = 0.f;
        #pragma unroll
        for (int j = 0; j < 2; ++j) {
            int n0 = j * 8 + (lane & 3) * 2;
            float b2a = b2[n0], b2b = b2[n0 + 1];
            float b3a = b3[n0], b3b = b3[n0 + 1];
            s0 += (acc[j][0] + b2a) * (acc[j + 2][0] + b3a)
                + (acc[j][1] + b2b) * (acc[j + 2][1] + b3b);
            s1 += (acc[j][2] + b2a) * (acc[j + 2][2] + b3a)
                + (acc[j][3] + b2b) * (acc[j + 2][3] + b3b);
        }
        s0 += __shfl_xor_sync(0xffffffffu, s0, 1);
        s0 += __shfl_xor_sync(0xffffffffu, s0, 2);
        s1 += __shfl_xor_sync(0xffffffffu, s1, 1);
        s1 += __shfl_xor_sync(0xffffffffu, s1, 2);
        if ((lane & 3) == 0) {
            int r = rbase + wid * 16 + (lane >> 2);
            g_s[r]     = s0;
            g_s[r + 8] = s1;
        }
        asm volatile("bar.sync 1, 256;" ::: "memory");
        if (tid == 0) {
            __threadfence();
            atomicExch(&g_s_flag[mb], 1);
        }
        return;
    }

    // ==================== GEMM CTA ====================
    const int cbase = (nbx - 1) * 128;

    if (wid == 8) {
        if (lane == 0) {
            const char* xhiB = (const char*)g_xhi;
            const char* whiB = (const char*)g_whi;
            int st = 0, ph = 1;
            for (int kt = 0; kt < NKT; ++kt) {
                MBARRIER_WAIT_PARITY(sEmpty + st * 8, ph);
                uint32_t fb = sFull + st * 8;
                MBARRIER_EXPECT_TX(fb, STAGE_B);
                uint32_t sb = sdyn + st * STAGE_B;
                size_t ax = ((size_t)(mb * NKT + kt)) * PART_B;
                size_t bw = ((size_t)((nbx - 1) * NKT + kt)) * PART_B;
                bulk_g2s(sb,          xhiB + ax, PART_B, fb);
                bulk_g2s(sb + PART_B, whiB + bw, PART_B, fb);
                if (++st == STAGES) { st = 0; ph ^= 1; }
            }
        }
        return;
    }

    // warps 0-7: 32x64 warp tiles (4 row groups x 2 col groups)
    const int warp_m = wid & 3;
    const int warp_n = wid >> 2;

    float acc[2][8][4];
    #pragma unroll
    for (int i = 0; i < 2; ++i)
        #pragma unroll
        for (int j = 0; j < 8; ++j)
            #pragma unroll
            for (int e = 0; e < 4; ++e)
                acc[i][j][e] = 0.f;

    uint32_t aRow[2], aSw[2];
    #pragma unroll
    for (int i = 0; i < 2; ++i) {
        int r = warp_m * 32 + i * 16 + (lane & 15);
        aRow[i] = (uint32_t)r * 128;
        aSw[i]  = (uint32_t)(r & 7);
    }
    uint32_t bRow[4], bSw[4];
    #pragma unroll
    for (int jj = 0; jj < 4; ++jj) {
        int r = warp_n * 64 + jj * 16 + (lane & 7) + ((lane >> 4) & 1) * 8;
        bRow[jj] = (uint32_t)r * 128;
        bSw[jj]  = (uint32_t)(r & 7);
    }
    const uint32_t ac0 = (uint32_t)(lane >> 4);
    const uint32_t bc0 = (uint32_t)((lane >> 3) & 1);

    int st = 0, ph = 0;
    for (int kt = 0; kt < NKT; ++kt) {
        MBARRIER_WAIT_PARITY(sFull + st * 8, ph);
        const uint32_t ah = sdyn + st * STAGE_B;
        const uint32_t bh = ah + PART_B;

        #pragma unroll
        for (int kk = 0; kk < 4; ++kk) {
            uint32_t Ah[2][4], Bf[4][4];
            const uint32_t ca = kk * 2 + ac0;
            const uint32_t cb = kk * 2 + bc0;
            #pragma unroll
            for (int i = 0; i < 2; ++i)
                ldsm_x4(Ah[i], ah + aRow[i] + ((ca ^ aSw[i]) << 4));
            #pragma unroll
            for (int jj = 0; jj < 4; ++jj)
                ldsm_x4(Bf[jj], bh + bRow[jj] + ((cb ^ bSw[jj]) << 4));
            #pragma unroll
            for (int i = 0; i < 2; ++i)
                #pragma unroll
                for (int j = 0; j < 8; ++j)
                    mma16816h(acc[i][j], Ah[i], &Bf[j >> 1][(j & 1) * 2]);
        }
        if (lane == 0) MBARRIER_ARRIVE(sEmpty + st * 8);
        if (++st == STAGES) { st = 0; ph ^= 1; }
    }

    // wait for s (long since done in the common case)
    {
        volatile int* f = (volatile int*)&g_s_flag[mb];
        while (*f == 0) {}
        __threadfence();
    }

    // epilogue: y = x * softplus(acc + b1) * s
    #pragma unroll
    for (int i = 0; i < 2; ++i) {
        const int r0 = rbase + warp_m * 32 + i * 16 + (lane >> 2);
        const int r1 = r0 + 8;
        const float s0 = g_s[r0], s1 = g_s[r1];
        #pragma unroll
        for (int j = 0; j < 8; ++j) {
            const int c = cbase + warp_n * 64 + j * 8 + (lane & 3) * 2;
            float2 bv = *reinterpret_cast<const float2*>(b1 + c);
            float2 x0 = *reinterpret_cast<const float2*>(x + (size_t)r0 * DDIM + c);
            float2 x1 = *reinterpret_cast<const float2*>(x + (size_t)r1 * DDIM + c);
            float2 o0, o1;
            o0.x = x0.x * softplusf(acc[i][j][0] + bv.x) * s0;
            o0.y = x0.y * softplusf(acc[i][j][1] + bv.y) * s0;
            o1.x = x1.x * softplusf(acc[i][j][2] + bv.x) * s1;
            o1.y = x1.y * softplusf(acc[i][j][3] + bv.y) * s1;
            *reinterpret_cast<float2*>(y + (size_t)r0 * DDIM + c) = o0;
            *reinterpret_cast<float2*>(y + (size_t)r1 * DDIM + c) = o1;
        }
    }
}

// ---------------------------------------------------------------------------
extern "C" void kernel_launch(void* const* d_in, const int* in_sizes, int n_in,
                              void* d_out, int out_size)
{
    const float* x  = (const float*)d_in[0];
    const float* W1 = (const float*)d_in[1];
    const float* b1 = (const float*)d_in[2];
    const float* W2 = (const float*)d_in[3];
    const float* b2 = (const float*)d_in[4];
    const float* W3 = (const float*)d_in[5];
    const float* b3 = (const float*)d_in[6];
    // d_in[7] = A is mathematically dead (multiplies zero-initialized h).
    float* y = (float*)d_out;

    cudaFuncSetAttribute(gemm_kernel,
                         cudaFuncAttributeMaxDynamicSharedMemorySize, GEMM_SMEM);

    prep_kernel<<<656, 256>>>(x, W1, W2, W3);

    dim3 grid(9, TOKENS / 128);   // x=0: s-CTAs; x=1..8: GEMM
    gemm_kernel<<<grid, 288, GEMM_SMEM>>>(x, b1, b2, b3, y);
}

// round 16
// speedup vs baseline: 1.0996x; 1.0996x over previous
#include <cuda_runtime.h>
#include <cuda_fp16.h>
#include <math.h>
#include <stdint.h>

#define TOKENS 4096
#define DDIM   1024

// ---------------------------------------------------------------------------
// scratch (__device__ globals; no cudaMalloc allowed)
// fp16 tiles, 128 rows x 64 cols = 16KB, SW128-pre-swizzled
// x: 32 mb x 16 kt = 512 tiles;  W1: 8 nb x 16 kt = 128 tiles
// w23: 16 kt tiles of 32 rows x 64 cols (rows 0-15 = W2, 16-31 = W3), 4KB each
// ---------------------------------------------------------------------------
__device__ float g_s[TOKENS];
__device__ int   g_s_flag[32];
__device__ __align__(1024) uint4 g_xhi[512 * 1024];
__device__ __align__(1024) uint4 g_whi[128 * 1024];
__device__ __align__(1024) uint4 g_w23[16 * 256];

// fast softplus: 2 MUFU + 2 FMUL. For z>15, exp(z) overflow-safe shortcut.
__device__ __forceinline__ float softplusf(float z) {
    if (z > 15.0f) return z;
    return __logf(1.0f + __expf(z));
}

__device__ __forceinline__ uint32_t smem_u32(const void* p) {
    uint32_t a;
    asm("{ .reg .u64 t; cvta.to.shared.u64 t, %1; cvt.u32.u64 %0, t; }"
        : "=r"(a) : "l"(p));
    return a;
}

#define MBARRIER_INIT(addr, cnt) \
    asm volatile("mbarrier.init.shared.b64 [%0], %1;" :: "r"(addr), "r"(cnt) : "memory")
#define MBARRIER_EXPECT_TX(addr, bytes) \
    asm volatile("mbarrier.arrive.expect_tx.shared.b64 _, [%0], %1;" \
        :: "r"(addr), "r"(bytes) : "memory")
#define MBARRIER_ARRIVE(addr) \
    asm volatile("mbarrier.arrive.shared.b64 _, [%0];" :: "r"(addr) : "memory")

#define MBARRIER_WAIT_PARITY(addr, parity) do { \
    uint32_t _m = (addr); uint32_t _p = (parity); uint32_t _d; \
    asm volatile("{\n\t.reg .pred p;\n\t" \
        "mbarrier.try_wait.parity.acquire.cta.shared::cta.b64 p, [%1], %2;\n\t" \
        "selp.b32 %0, 1, 0, p;\n\t}" : "=r"(_d) : "r"(_m), "r"(_p) : "memory"); \
    if (!_d) { \
        asm volatile("{\n\t.reg .pred P1;\n\t" \
            "WL_%=:\n\t" \
            "mbarrier.try_wait.parity.acquire.cta.shared::cta.b64 P1, [%0], %1, 0x989680;\n\t" \
            "@P1 bra.uni WD_%=;\n\t" \
            "bra.uni WL_%=;\n\t" \
            "WD_%=:\n\t}" :: "r"(_m), "r"(_p) : "memory"); \
    } \
} while (0)

__device__ __forceinline__ void bulk_g2s(uint32_t dst, const void* src,
                                         uint32_t bytes, uint32_t mbar) {
    asm volatile(
        "cp.async.bulk.shared::cluster.global.mbarrier::complete_tx::bytes "
        "[%0], [%1], %2, [%3];"
        :: "r"(dst), "l"(src), "r"(bytes), "r"(mbar) : "memory");
}

__device__ __forceinline__ void ldsm_x4(uint32_t* r, uint32_t addr) {
    asm volatile("ldmatrix.sync.aligned.m8n8.x4.shared.b16 {%0,%1,%2,%3}, [%4];"
                 : "=r"(r[0]), "=r"(r[1]), "=r"(r[2]), "=r"(r[3]) : "r"(addr));
}
__device__ __forceinline__ void mma16816h(float* d, const uint32_t* a,
                                          const uint32_t* b) {
    asm volatile(
        "mma.sync.aligned.m16n8k16.row.col.f32.f16.f16.f32 "
        "{%0,%1,%2,%3}, {%4,%5,%6,%7}, {%8,%9}, {%0,%1,%2,%3};"
        : "+f"(d[0]), "+f"(d[1]), "+f"(d[2]), "+f"(d[3])
        : "r"(a[0]), "r"(a[1]), "r"(a[2]), "r"(a[3]), "r"(b[0]), "r"(b[1]));
}

// ---------------------------------------------------------------------------
// Kernel 0 (prep = convert only):
//  blocks 0..511   : downcast x to fp16 128x64 tiles (SW128-pre-swizzled)
//  blocks 512..639 : downcast W1 likewise
//  blocks 640..655 : downcast W2/W3 into 32x64 w23 tiles (block = kt)
//  block  655 also zeroes g_s_flag
// ---------------------------------------------------------------------------
__global__ __launch_bounds__(256) void prep_kernel(
    const float* __restrict__ X, const float* __restrict__ W,
    const float* __restrict__ W2, const float* __restrict__ W3)
{
    const int bid = blockIdx.x;
    const int tid = threadIdx.x;

    if (bid >= 640) {
        // ---- w23 tiles ----
        const int kt = bid - 640;
        if (bid == 655 && tid >= 224) {   // zero flags (32 threads)
            g_s_flag[tid - 224] = 0;
        }
        int row = tid >> 3, c8 = tid & 7;
        const float* src = (row < 16) ? &W2[(size_t)row * DDIM]
                                      : &W3[(size_t)(row - 16) * DDIM];
        const float* p = src + kt * 64 + c8 * 8;
        float4 v0 = *reinterpret_cast<const float4*>(p);
        float4 v1 = *reinterpret_cast<const float4*>(p + 4);
        float v[8] = {v0.x, v0.y, v0.z, v0.w, v1.x, v1.y, v1.z, v1.w};
        uint32_t ph[4];
        #pragma unroll
        for (int i = 0; i < 4; ++i) {
            __half h0 = __float2half_rn(v[2 * i]);
            __half h1 = __float2half_rn(v[2 * i + 1]);
            ph[i] = (uint32_t)__half_as_ushort(h0) |
                    ((uint32_t)__half_as_ushort(h1) << 16);
        }
        uint32_t off = (uint32_t)(row * 128 + c8 * 16);
        off ^= ((off >> 3) & 0x70);
        g_w23[kt * 256 + (off >> 4)] = make_uint4(ph[0], ph[1], ph[2], ph[3]);
        return;
    }

    // ---- x / W1 tiles ----
    const float* src;
    uint4* dhi;
    if (bid < 512) {
        int mb = bid >> 4, kb = bid & 15;
        src = X + (size_t)mb * 128 * DDIM + kb * 64;
        dhi = g_xhi + (size_t)bid * 1024;
    } else {
        int t = bid - 512;
        int nb = t >> 4, kb = t & 15;
        src = W + (size_t)nb * 128 * DDIM + kb * 64;
        dhi = g_whi + (size_t)t * 1024;
    }
    #pragma unroll
    for (int it = 0; it < 4; ++it) {
        int c = tid + it * 256;
        int row = c >> 3, c8 = c & 7;
        const float* p = src + (size_t)row * DDIM + c8 * 8;
        float4 v0 = *reinterpret_cast<const float4*>(p);
        float4 v1 = *reinterpret_cast<const float4*>(p + 4);
        float v[8] = {v0.x, v0.y, v0.z, v0.w, v1.x, v1.y, v1.z, v1.w};
        uint32_t ph[4];
        #pragma unroll
        for (int i = 0; i < 4; ++i) {
            __half h0 = __float2half_rn(v[2 * i]);
            __half h1 = __float2half_rn(v[2 * i + 1]);
            ph[i] = (uint32_t)__half_as_ushort(h0) |
                    ((uint32_t)__half_as_ushort(h1) << 16);
        }
        uint32_t off = (uint32_t)(row * 128 + c8 * 16);
        off ^= ((off >> 3) & 0x70);   // SW128 swizzle, pre-applied
        dhi[off >> 4] = make_uint4(ph[0], ph[1], ph[2], ph[3]);
    }
}

// ---------------------------------------------------------------------------
// Kernel 1: fused GEMM + s computation (R14 config + fast epilogue).
// grid (9, 32): blockIdx.x == 0 -> s-CTA for row-block mb; else GEMM CTA.
// GEMM: D = xhi @ whi^T; y = xhi * softplus(D + b1) * s  (epilogue reads fp16 x)
// s-CTA: [Bm|Cm] = xhi @ w23^T (N=32); s = sum_n (Bm+b2)(Cm+b3); flag release.
// BM=BN=128, BK=64, 6-stage bulk pipeline, 544 threads.
// ---------------------------------------------------------------------------
#define NKT 16                    // 1024 / 64
#define STAGES 6
#define PART_B 16384              // one 128x64 fp16 tile
#define STAGE_B (2 * PART_B)      // 32KB
#define GEMM_SMEM (STAGES * STAGE_B)   // 196608
#define S_STAGE_TX (16384 + 4096)

__global__ __launch_bounds__(544, 1) void gemm_kernel(
    const float* __restrict__ b1,
    const float* __restrict__ b2,
    const float* __restrict__ b3,
    float* __restrict__ y)
{
    extern __shared__ __align__(1024) char smem[];
    __shared__ __align__(8) uint64_t mbar[2 * STAGES];

    const uint32_t sdyn = smem_u32(smem);
    const uint32_t sFull  = smem_u32(&mbar[0]);
    const uint32_t sEmpty = smem_u32(&mbar[STAGES]);

    const int tid  = threadIdx.x;
    const int wid  = tid >> 5;
    const int lane = tid & 31;
    const int nbx = blockIdx.x;         // 0 = s-CTA, 1..8 = GEMM
    const int mb  = blockIdx.y;         // 0..31
    const int rbase = mb * 128;
    const bool is_s = (nbx == 0);

    if (tid == 0) {
        #pragma unroll
        for (int s = 0; s < STAGES; ++s) {
            MBARRIER_INIT(sFull  + s * 8, 1);
            MBARRIER_INIT(sEmpty + s * 8, is_s ? 8 : 16);
        }
    }
    __syncthreads();

    if (is_s) {
        // ==================== s-CTA ====================
        if (wid == 16) {
            if (lane == 0) {
                const char* xhiB = (const char*)g_xhi;
                const char* w23B = (const char*)g_w23;
                int st = 0, ph = 1;
                for (int kt = 0; kt < NKT; ++kt) {
                    MBARRIER_WAIT_PARITY(sEmpty + st * 8, ph);
                    uint32_t fb = sFull + st * 8;
                    MBARRIER_EXPECT_TX(fb, S_STAGE_TX);
                    uint32_t sb = sdyn + st * STAGE_B;
                    bulk_g2s(sb, xhiB + ((size_t)(mb * NKT + kt)) * PART_B,
                             PART_B, fb);
                    bulk_g2s(sb + PART_B, w23B + (size_t)kt * 4096, 4096, fb);
                    if (++st == STAGES) { st = 0; ph ^= 1; }
                }
            }
            return;
        }
        if (wid >= 8) return;   // warps 8-15 idle in s-CTA

        float acc[4][4];
        #pragma unroll
        for (int j = 0; j < 4; ++j)
            #pragma unroll
            for (int e = 0; e < 4; ++e)
                acc[j][e] = 0.f;

        const uint32_t aRow = (uint32_t)(wid * 16 + (lane & 15)) * 128;
        const uint32_t aSw  = (uint32_t)((wid * 16 + (lane & 15)) & 7);
        uint32_t bRow[2], bSw[2];
        #pragma unroll
        for (int jj = 0; jj < 2; ++jj) {
            int r = jj * 16 + (lane & 7) + ((lane >> 4) & 1) * 8;
            bRow[jj] = (uint32_t)r * 128;
            bSw[jj]  = (uint32_t)(r & 7);
        }
        const uint32_t ac0 = (uint32_t)(lane >> 4);
        const uint32_t bc0 = (uint32_t)((lane >> 3) & 1);

        int st = 0, ph = 0;
        for (int kt = 0; kt < NKT; ++kt) {
            MBARRIER_WAIT_PARITY(sFull + st * 8, ph);
            const uint32_t ah = sdyn + st * STAGE_B;
            const uint32_t bh = ah + PART_B;
            #pragma unroll
            for (int kk = 0; kk < 4; ++kk) {
                uint32_t Ah[4], Bf[2][4];
                const uint32_t ca = kk * 2 + ac0;
                const uint32_t cb = kk * 2 + bc0;
                ldsm_x4(Ah, ah + aRow + ((ca ^ aSw) << 4));
                #pragma unroll
                for (int jj = 0; jj < 2; ++jj)
                    ldsm_x4(Bf[jj], bh + bRow[jj] + ((cb ^ bSw[jj]) << 4));
                #pragma unroll
                for (int j = 0; j < 4; ++j)
                    mma16816h(acc[j], Ah, &Bf[j >> 1][(j & 1) * 2]);
            }
            if (lane == 0) MBARRIER_ARRIVE(sEmpty + st * 8);
            if (++st == STAGES) { st = 0; ph ^= 1; }
        }

        // s = sum_n (Bm + b2)(Cm + b3); cols 0-15 = Bm, 16-31 = Cm
        float s0 = 0.f, s1 = 0.f;
        #pragma unroll
        for (int j = 0; j < 2; ++j) {
            int n0 = j * 8 + (lane & 3) * 2;
            float b2a = b2[n0], b2b = b2[n0 + 1];
            float b3a = b3[n0], b3b = b3[n0 + 1];
            s0 += (acc[j][0] + b2a) * (acc[j + 2][0] + b3a)
                + (acc[j][1] + b2b) * (acc[j + 2][1] + b3b);
            s1 += (acc[j][2] + b2a) * (acc[j + 2][2] + b3a)
                + (acc[j][3] + b2b) * (acc[j + 2][3] + b3b);
        }
        s0 += __shfl_xor_sync(0xffffffffu, s0, 1);
        s0 += __shfl_xor_sync(0xffffffffu, s0, 2);
        s1 += __shfl_xor_sync(0xffffffffu, s1, 1);
        s1 += __shfl_xor_sync(0xffffffffu, s1, 2);
        if ((lane & 3) == 0) {
            int r = rbase + wid * 16 + (lane >> 2);
            g_s[r]     = s0;
            g_s[r + 8] = s1;
        }
        asm volatile("bar.sync 1, 256;" ::: "memory");
        if (tid == 0) {
            __threadfence();
            atomicExch(&g_s_flag[mb], 1);
        }
        return;
    }

    // ==================== GEMM CTA ====================
    const int cbase = (nbx - 1) * 128;

    if (wid == 16) {
        if (lane == 0) {
            const char* xhiB = (const char*)g_xhi;
            const char* whiB = (const char*)g_whi;
            int st = 0, ph = 1;
            for (int kt = 0; kt < NKT; ++kt) {
                MBARRIER_WAIT_PARITY(sEmpty + st * 8, ph);
                uint32_t fb = sFull + st * 8;
                MBARRIER_EXPECT_TX(fb, STAGE_B);
                uint32_t sb = sdyn + st * STAGE_B;
                size_t ax = ((size_t)(mb * NKT + kt)) * PART_B;
                size_t bw = ((size_t)((nbx - 1) * NKT + kt)) * PART_B;
                bulk_g2s(sb,          xhiB + ax, PART_B, fb);
                bulk_g2s(sb + PART_B, whiB + bw, PART_B, fb);
                if (++st == STAGES) { st = 0; ph ^= 1; }
            }
        }
        return;
    }

    const int warp_m = wid & 3;
    const int warp_n = wid >> 2;

    float acc[2][4][4];
    #pragma unroll
    for (int i = 0; i < 2; ++i)
        #pragma unroll
        for (int j = 0; j < 4; ++j)
            #pragma unroll
            for (int e = 0; e < 4; ++e)
                acc[i][j][e] = 0.f;

    uint32_t aRow[2], aSw[2];
    #pragma unroll
    for (int i = 0; i < 2; ++i) {
        int r = warp_m * 32 + i * 16 + (lane & 15);
        aRow[i] = (uint32_t)r * 128;
        aSw[i]  = (uint32_t)(r & 7);
    }
    uint32_t bRow[2], bSw[2];
    #pragma unroll
    for (int jj = 0; jj < 2; ++jj) {
        int r = warp_n * 32 + jj * 16 + (lane & 7) + ((lane >> 4) & 1) * 8;
        bRow[jj] = (uint32_t)r * 128;
        bSw[jj]  = (uint32_t)(r & 7);
    }
    const uint32_t ac0 = (uint32_t)(lane >> 4);
    const uint32_t bc0 = (uint32_t)((lane >> 3) & 1);

    int st = 0, ph = 0;
    for (int kt = 0; kt < NKT; ++kt) {
        MBARRIER_WAIT_PARITY(sFull + st * 8, ph);
        const uint32_t ah = sdyn + st * STAGE_B;
        const uint32_t bh = ah + PART_B;

        #pragma unroll
        for (int kk = 0; kk < 4; ++kk) {
            uint32_t Ah[2][4], Bf[2][4];
            const uint32_t ca = kk * 2 + ac0;
            const uint32_t cb = kk * 2 + bc0;
            #pragma unroll
            for (int i = 0; i < 2; ++i)
                ldsm_x4(Ah[i], ah + aRow[i] + ((ca ^ aSw[i]) << 4));
            #pragma unroll
            for (int jj = 0; jj < 2; ++jj)
                ldsm_x4(Bf[jj], bh + bRow[jj] + ((cb ^ bSw[jj]) << 4));
            #pragma unroll
            for (int i = 0; i < 2; ++i)
                #pragma unroll
                for (int j = 0; j < 4; ++j)
                    mma16816h(acc[i][j], Ah[i], &Bf[j >> 1][(j & 1) * 2]);
        }
        if (lane == 0) MBARRIER_ARRIVE(sEmpty + st * 8);
        if (++st == STAGES) { st = 0; ph ^= 1; }
    }

    // wait for s (long since done in the common case)
    {
        volatile int* f = (volatile int*)&g_s_flag[mb];
        while (*f == 0) {}
        __threadfence();
    }

    // epilogue: y = xhi * softplus(acc + b1) * s   (x read as fp16 from tiles)
    // column range of this warp lies in ONE kt tile: kt_e = (cbase+warp_n*32)/64
    const int kt_e   = (cbase + warp_n * 32) >> 6;
    const int colb   = (cbase + warp_n * 32) & 63;   // 0 or 32
    const char* xt = (const char*)(g_xhi + ((size_t)(mb * 16 + kt_e)) * 1024);

    #pragma unroll
    for (int i = 0; i < 2; ++i) {
        const int row0 = warp_m * 32 + i * 16 + (lane >> 2);   // in-tile row
        const int row1 = row0 + 8;
        const int r0 = rbase + row0;
        const int r1 = rbase + row1;
        const float s0 = g_s[r0], s1 = g_s[r1];
        #pragma unroll
        for (int j = 0; j < 4; ++j) {
            const int ci = colb + j * 8 + (lane & 3) * 2;      // in-tile col
            const int c  = cbase + warp_n * 32 + j * 8 + (lane & 3) * 2;
            uint32_t off0 = (uint32_t)(row0 * 128 + ci * 2);
            uint32_t off1 = (uint32_t)(row1 * 128 + ci * 2);
            off0 ^= ((off0 >> 3) & 0x70);
            off1 ^= ((off1 >> 3) & 0x70);
            __half2 xh0 = *reinterpret_cast<const __half2*>(xt + off0);
            __half2 xh1 = *reinterpret_cast<const __half2*>(xt + off1);
            float2 bv = *reinterpret_cast<const float2*>(b1 + c);
            float2 o0, o1;
            o0.x = __half2float(xh0.x) * softplusf(acc[i][j][0] + bv.x) * s0;
            o0.y = __half2float(xh0.y) * softplusf(acc[i][j][1] + bv.y) * s0;
            o1.x = __half2float(xh1.x) * softplusf(acc[i][j][2] + bv.x) * s1;
            o1.y = __half2float(xh1.y) * softplusf(acc[i][j][3] + bv.y) * s1;
            *reinterpret_cast<float2*>(y + (size_t)r0 * DDIM + c) = o0;
            *reinterpret_cast<float2*>(y + (size_t)r1 * DDIM + c) = o1;
        }
    }
}

// ---------------------------------------------------------------------------
extern "C" void kernel_launch(void* const* d_in, const int* in_sizes, int n_in,
                              void* d_out, int out_size)
{
    const float* x  = (const float*)d_in[0];
    const float* W1 = (const float*)d_in[1];
    const float* b1 = (const float*)d_in[2];
    const float* W2 = (const float*)d_in[3];
    const float* b2 = (const float*)d_in[4];
    const float* W3 = (const float*)d_in[5];
    const float* b3 = (const float*)d_in[6];
    // d_in[7] = A is mathematically dead (multiplies zero-initialized h).
    float* y = (float*)d_out;

    cudaFuncSetAttribute(gemm_kernel,
                         cudaFuncAttributeMaxDynamicSharedMemorySize, GEMM_SMEM);

    prep_kernel<<<656, 256>>>(x, W1, W2, W3);

    dim3 grid(9, TOKENS / 128);   // x=0: s-CTAs; x=1..8: GEMM
    gemm_kernel<<<grid, 544, GEMM_SMEM>>>(b1, b2, b3, y);
}

// round 17
// speedup vs baseline: 1.1062x; 1.0060x over previous
#include <cuda_runtime.h>
#include <cuda_fp16.h>
#include <math.h>
#include <stdint.h>

#define TOKENS 4096
#define DDIM   1024

// ---------------------------------------------------------------------------
// scratch (__device__ globals; no cudaMalloc allowed)
// fp16 tiles, 128 rows x 64 cols = 16KB, SW128-pre-swizzled
// x: 32 mb x 16 kt = 512 tiles;  W1: 8 nb x 16 kt = 128 tiles
// w23: 16 kt tiles of 32 rows x 64 cols (rows 0-15 = W2, 16-31 = W3), 4KB each
// ---------------------------------------------------------------------------
__device__ float g_s[TOKENS];
__device__ int   g_s_flag[32];
__device__ __align__(1024) uint4 g_xhi[512 * 1024];
__device__ __align__(1024) uint4 g_whi[128 * 1024];
__device__ __align__(1024) uint4 g_w23[16 * 256];

// fast softplus: 2 MUFU + 2 FMUL. For z>15, exp(z) overflow-safe shortcut.
__device__ __forceinline__ float softplusf(float z) {
    if (z > 15.0f) return z;
    return __logf(1.0f + __expf(z));
}

__device__ __forceinline__ uint32_t smem_u32(const void* p) {
    uint32_t a;
    asm("{ .reg .u64 t; cvta.to.shared.u64 t, %1; cvt.u32.u64 %0, t; }"
        : "=r"(a) : "l"(p));
    return a;
}

#define MBARRIER_INIT(addr, cnt) \
    asm volatile("mbarrier.init.shared.b64 [%0], %1;" :: "r"(addr), "r"(cnt) : "memory")
#define MBARRIER_EXPECT_TX(addr, bytes) \
    asm volatile("mbarrier.arrive.expect_tx.shared.b64 _, [%0], %1;" \
        :: "r"(addr), "r"(bytes) : "memory")
#define MBARRIER_ARRIVE(addr) \
    asm volatile("mbarrier.arrive.shared.b64 _, [%0];" :: "r"(addr) : "memory")

#define MBARRIER_WAIT_PARITY(addr, parity) do { \
    uint32_t _m = (addr); uint32_t _p = (parity); uint32_t _d; \
    asm volatile("{\n\t.reg .pred p;\n\t" \
        "mbarrier.try_wait.parity.acquire.cta.shared::cta.b64 p, [%1], %2;\n\t" \
        "selp.b32 %0, 1, 0, p;\n\t}" : "=r"(_d) : "r"(_m), "r"(_p) : "memory"); \
    if (!_d) { \
        asm volatile("{\n\t.reg .pred P1;\n\t" \
            "WL_%=:\n\t" \
            "mbarrier.try_wait.parity.acquire.cta.shared::cta.b64 P1, [%0], %1, 0x989680;\n\t" \
            "@P1 bra.uni WD_%=;\n\t" \
            "bra.uni WL_%=;\n\t" \
            "WD_%=:\n\t}" :: "r"(_m), "r"(_p) : "memory"); \
    } \
} while (0)

__device__ __forceinline__ void bulk_g2s(uint32_t dst, const void* src,
                                         uint32_t bytes, uint32_t mbar) {
    asm volatile(
        "cp.async.bulk.shared::cluster.global.mbarrier::complete_tx::bytes "
        "[%0], [%1], %2, [%3];"
        :: "r"(dst), "l"(src), "r"(bytes), "r"(mbar) : "memory");
}

__device__ __forceinline__ void ldsm_x4(uint32_t* r, uint32_t addr) {
    asm volatile("ldmatrix.sync.aligned.m8n8.x4.shared.b16 {%0,%1,%2,%3}, [%4];"
                 : "=r"(r[0]), "=r"(r[1]), "=r"(r[2]), "=r"(r[3]) : "r"(addr));
}
__device__ __forceinline__ void mma16816h(float* d, const uint32_t* a,
                                          const uint32_t* b) {
    asm volatile(
        "mma.sync.aligned.m16n8k16.row.col.f32.f16.f16.f32 "
        "{%0,%1,%2,%3}, {%4,%5,%6,%7}, {%8,%9}, {%0,%1,%2,%3};"
        : "+f"(d[0]), "+f"(d[1]), "+f"(d[2]), "+f"(d[3])
        : "r"(a[0]), "r"(a[1]), "r"(a[2]), "r"(a[3]), "r"(b[0]), "r"(b[1]));
}

// ---------------------------------------------------------------------------
// Kernel 0 (prep = convert only):
//  blocks 0..511   : downcast x to fp16 128x64 tiles (SW128-pre-swizzled)
//  blocks 512..639 : downcast W1 likewise
//  blocks 640..655 : downcast W2/W3 into 32x64 w23 tiles (block = kt)
//  block  655 also zeroes g_s_flag
// ---------------------------------------------------------------------------
__global__ __launch_bounds__(256) void prep_kernel(
    const float* __restrict__ X, const float* __restrict__ W,
    const float* __restrict__ W2, const float* __restrict__ W3)
{
    const int bid = blockIdx.x;
    const int tid = threadIdx.x;

    if (bid >= 640) {
        // ---- w23 tiles ----
        const int kt = bid - 640;
        if (bid == 655 && tid >= 224) {   // zero flags (32 threads)
            g_s_flag[tid - 224] = 0;
        }
        int row = tid >> 3, c8 = tid & 7;
        const float* src = (row < 16) ? &W2[(size_t)row * DDIM]
                                      : &W3[(size_t)(row - 16) * DDIM];
        const float* p = src + kt * 64 + c8 * 8;
        float4 v0 = *reinterpret_cast<const float4*>(p);
        float4 v1 = *reinterpret_cast<const float4*>(p + 4);
        float v[8] = {v0.x, v0.y, v0.z, v0.w, v1.x, v1.y, v1.z, v1.w};
        uint32_t ph[4];
        #pragma unroll
        for (int i = 0; i < 4; ++i) {
            __half h0 = __float2half_rn(v[2 * i]);
            __half h1 = __float2half_rn(v[2 * i + 1]);
            ph[i] = (uint32_t)__half_as_ushort(h0) |
                    ((uint32_t)__half_as_ushort(h1) << 16);
        }
        uint32_t off = (uint32_t)(row * 128 + c8 * 16);
        off ^= ((off >> 3) & 0x70);
        g_w23[kt * 256 + (off >> 4)] = make_uint4(ph[0], ph[1], ph[2], ph[3]);
        return;
    }

    // ---- x / W1 tiles ----
    const float* src;
    uint4* dhi;
    if (bid < 512) {
        int mb = bid >> 4, kb = bid & 15;
        src = X + (size_t)mb * 128 * DDIM + kb * 64;
        dhi = g_xhi + (size_t)bid * 1024;
    } else {
        int t = bid - 512;
        int nb = t >> 4, kb = t & 15;
        src = W + (size_t)nb * 128 * DDIM + kb * 64;
        dhi = g_whi + (size_t)t * 1024;
    }
    #pragma unroll
    for (int it = 0; it < 4; ++it) {
        int c = tid + it * 256;
        int row = c >> 3, c8 = c & 7;
        const float* p = src + (size_t)row * DDIM + c8 * 8;
        float4 v0 = *reinterpret_cast<const float4*>(p);
        float4 v1 = *reinterpret_cast<const float4*>(p + 4);
        float v[8] = {v0.x, v0.y, v0.z, v0.w, v1.x, v1.y, v1.z, v1.w};
        uint32_t ph[4];
        #pragma unroll
        for (int i = 0; i < 4; ++i) {
            __half h0 = __float2half_rn(v[2 * i]);
            __half h1 = __float2half_rn(v[2 * i + 1]);
            ph[i] = (uint32_t)__half_as_ushort(h0) |
                    ((uint32_t)__half_as_ushort(h1) << 16);
        }
        uint32_t off = (uint32_t)(row * 128 + c8 * 16);
        off ^= ((off >> 3) & 0x70);   // SW128 swizzle, pre-applied
        dhi[off >> 4] = make_uint4(ph[0], ph[1], ph[2], ph[3]);
    }
}

// ---------------------------------------------------------------------------
// Kernel 1: fused GEMM + s computation.
// grid (9, 32): blockIdx.x == 0 -> s-CTA for row-block mb; else GEMM CTA.
// GEMM: D = xhi @ whi^T; y = xhi * softplus(D + b1) * s
// s-CTA: [Bm|Cm] = xhi @ w23^T (N=32); s = sum_n (Bm+b2)(Cm+b3); flag release.
// BK=128 per stage (2 kt tiles), 3-stage pipeline (64KB/stage), 544 threads.
// Fragments register double-buffered: ldsm kk+1 issues before MMAs of kk.
// ---------------------------------------------------------------------------
#define NKO 8                     // 1024 / 128
#define STAGES 3
#define TILE_B 16384              // one 128x64 fp16 tile
#define STAGE_B (4 * TILE_B)      // Ax2 + Bx2 = 64KB
#define GEMM_SMEM (STAGES * STAGE_B)   // 196608
#define S_STAGE_TX (32768 + 8192)

__global__ __launch_bounds__(544, 1) void gemm_kernel(
    const float* __restrict__ b1,
    const float* __restrict__ b2,
    const float* __restrict__ b3,
    float* __restrict__ y)
{
    extern __shared__ __align__(1024) char smem[];
    __shared__ __align__(8) uint64_t mbar[2 * STAGES];

    const uint32_t sdyn = smem_u32(smem);
    const uint32_t sFull  = smem_u32(&mbar[0]);
    const uint32_t sEmpty = smem_u32(&mbar[STAGES]);

    const int tid  = threadIdx.x;
    const int wid  = tid >> 5;
    const int lane = tid & 31;
    const int nbx = blockIdx.x;         // 0 = s-CTA, 1..8 = GEMM
    const int mb  = blockIdx.y;         // 0..31
    const int rbase = mb * 128;
    const bool is_s = (nbx == 0);

    if (tid == 0) {
        #pragma unroll
        for (int s = 0; s < STAGES; ++s) {
            MBARRIER_INIT(sFull  + s * 8, 1);
            MBARRIER_INIT(sEmpty + s * 8, is_s ? 8 : 16);
        }
    }
    __syncthreads();

    if (is_s) {
        // ==================== s-CTA ====================
        if (wid == 16) {
            if (lane == 0) {
                const char* xhiB = (const char*)g_xhi;
                const char* w23B = (const char*)g_w23;
                int st = 0, ph = 1;
                for (int ko = 0; ko < NKO; ++ko) {
                    MBARRIER_WAIT_PARITY(sEmpty + st * 8, ph);
                    uint32_t fb = sFull + st * 8;
                    MBARRIER_EXPECT_TX(fb, S_STAGE_TX);
                    uint32_t sb = sdyn + st * STAGE_B;
                    bulk_g2s(sb, xhiB + ((size_t)(mb * 16 + ko * 2)) * TILE_B,
                             2 * TILE_B, fb);
                    bulk_g2s(sb + 2 * TILE_B,
                             w23B + (size_t)(ko * 2) * 4096, 8192, fb);
                    if (++st == STAGES) { st = 0; ph ^= 1; }
                }
            }
            return;
        }
        if (wid >= 8) return;   // warps 8-15 idle in s-CTA

        float acc[4][4];
        #pragma unroll
        for (int j = 0; j < 4; ++j)
            #pragma unroll
            for (int e = 0; e < 4; ++e)
                acc[j][e] = 0.f;

        const uint32_t aRow = (uint32_t)(wid * 16 + (lane & 15)) * 128;
        const uint32_t aSw  = (uint32_t)((wid * 16 + (lane & 15)) & 7);
        uint32_t bRow[2], bSw[2];
        #pragma unroll
        for (int jj = 0; jj < 2; ++jj) {
            int r = jj * 16 + (lane & 7) + ((lane >> 4) & 1) * 8;
            bRow[jj] = (uint32_t)r * 128;
            bSw[jj]  = (uint32_t)(r & 7);
        }
        const uint32_t ac0 = (uint32_t)(lane >> 4);
        const uint32_t bc0 = (uint32_t)((lane >> 3) & 1);

        int st = 0, ph = 0;
        for (int ko = 0; ko < NKO; ++ko) {
            MBARRIER_WAIT_PARITY(sFull + st * 8, ph);
            const uint32_t sb = sdyn + st * STAGE_B;
            #pragma unroll
            for (int kk = 0; kk < 8; ++kk) {
                const uint32_t ah = sb + (kk >> 2) * TILE_B;
                const uint32_t bh = sb + 2 * TILE_B + (kk >> 2) * 4096;
                uint32_t Ah[4], Bf[2][4];
                const uint32_t ca = (kk & 3) * 2 + ac0;
                const uint32_t cb = (kk & 3) * 2 + bc0;
                ldsm_x4(Ah, ah + aRow + ((ca ^ aSw) << 4));
                #pragma unroll
                for (int jj = 0; jj < 2; ++jj)
                    ldsm_x4(Bf[jj], bh + bRow[jj] + ((cb ^ bSw[jj]) << 4));
                #pragma unroll
                for (int j = 0; j < 4; ++j)
                    mma16816h(acc[j], Ah, &Bf[j >> 1][(j & 1) * 2]);
            }
            if (lane == 0) MBARRIER_ARRIVE(sEmpty + st * 8);
            if (++st == STAGES) { st = 0; ph ^= 1; }
        }

        // s = sum_n (Bm + b2)(Cm + b3); cols 0-15 = Bm, 16-31 = Cm
        float s0 = 0.f, s1 = 0.f;
        #pragma unroll
        for (int j = 0; j < 2; ++j) {
            int n0 = j * 8 + (lane & 3) * 2;
            float b2a = b2[n0], b2b = b2[n0 + 1];
            float b3a = b3[n0], b3b = b3[n0 + 1];
            s0 += (acc[j][0] + b2a) * (acc[j + 2][0] + b3a)
                + (acc[j][1] + b2b) * (acc[j + 2][1] + b3b);
            s1 += (acc[j][2] + b2a) * (acc[j + 2][2] + b3a)
                + (acc[j][3] + b2b) * (acc[j + 2][3] + b3b);
        }
        s0 += __shfl_xor_sync(0xffffffffu, s0, 1);
        s0 += __shfl_xor_sync(0xffffffffu, s0, 2);
        s1 += __shfl_xor_sync(0xffffffffu, s1, 1);
        s1 += __shfl_xor_sync(0xffffffffu, s1, 2);
        if ((lane & 3) == 0) {
            int r = rbase + wid * 16 + (lane >> 2);
            g_s[r]     = s0;
            g_s[r + 8] = s1;
        }
        asm volatile("bar.sync 1, 256;" ::: "memory");
        if (tid == 0) {
            __threadfence();
            atomicExch(&g_s_flag[mb], 1);
        }
        return;
    }

    // ==================== GEMM CTA ====================
    const int cbase = (nbx - 1) * 128;

    if (wid == 16) {
        if (lane == 0) {
            const char* xhiB = (const char*)g_xhi;
            const char* whiB = (const char*)g_whi;
            int st = 0, ph = 1;
            for (int ko = 0; ko < NKO; ++ko) {
                MBARRIER_WAIT_PARITY(sEmpty + st * 8, ph);
                uint32_t fb = sFull + st * 8;
                MBARRIER_EXPECT_TX(fb, STAGE_B);
                uint32_t sb = sdyn + st * STAGE_B;
                size_t ax = ((size_t)(mb * 16 + ko * 2)) * TILE_B;
                size_t bw = ((size_t)((nbx - 1) * 16 + ko * 2)) * TILE_B;
                bulk_g2s(sb,              xhiB + ax, 2 * TILE_B, fb);
                bulk_g2s(sb + 2 * TILE_B, whiB + bw, 2 * TILE_B, fb);
                if (++st == STAGES) { st = 0; ph ^= 1; }
            }
        }
        return;
    }

    const int warp_m = wid & 3;
    const int warp_n = wid >> 2;

    float acc[2][4][4];
    #pragma unroll
    for (int i = 0; i < 2; ++i)
        #pragma unroll
        for (int j = 0; j < 4; ++j)
            #pragma unroll
            for (int e = 0; e < 4; ++e)
                acc[i][j][e] = 0.f;

    uint32_t aRow[2], aSw[2];
    #pragma unroll
    for (int i = 0; i < 2; ++i) {
        int r = warp_m * 32 + i * 16 + (lane & 15);
        aRow[i] = (uint32_t)r * 128;
        aSw[i]  = (uint32_t)(r & 7);
    }
    uint32_t bRow[2], bSw[2];
    #pragma unroll
    for (int jj = 0; jj < 2; ++jj) {
        int r = warp_n * 32 + jj * 16 + (lane & 7) + ((lane >> 4) & 1) * 8;
        bRow[jj] = (uint32_t)r * 128;
        bSw[jj]  = (uint32_t)(r & 7);
    }
    const uint32_t ac0 = (uint32_t)(lane >> 4);
    const uint32_t bc0 = (uint32_t)((lane >> 3) & 1);

    // double-buffered fragments
    uint32_t Ah[2][2][4], Bf[2][2][4];

    #define LOAD_FRAGS(bf, sb, kk) do {                                      \
        const uint32_t _ts = (uint32_t)(((kk) >> 2) * TILE_B);               \
        const uint32_t _ca = (uint32_t)(((kk) & 3) * 2) + ac0;               \
        const uint32_t _cb = (uint32_t)(((kk) & 3) * 2) + bc0;               \
        _Pragma("unroll")                                                    \
        for (int _i = 0; _i < 2; ++_i)                                       \
            ldsm_x4(Ah[bf][_i], (sb) + _ts + aRow[_i] + ((_ca ^ aSw[_i]) << 4)); \
        _Pragma("unroll")                                                    \
        for (int _jj = 0; _jj < 2; ++_jj)                                    \
            ldsm_x4(Bf[bf][_jj], (sb) + 2 * TILE_B + _ts + bRow[_jj]         \
                    + ((_cb ^ bSw[_jj]) << 4));                              \
    } while (0)

    #define DO_MMAS(bf) do {                                                 \
        _Pragma("unroll")                                                    \
        for (int _i = 0; _i < 2; ++_i)                                       \
            _Pragma("unroll")                                                \
            for (int _j = 0; _j < 4; ++_j)                                   \
                mma16816h(acc[_i][_j], Ah[bf][_i], &Bf[bf][_j >> 1][(_j & 1) * 2]); \
    } while (0)

    int st = 0, ph = 0;
    MBARRIER_WAIT_PARITY(sFull + 0, 0);
    LOAD_FRAGS(0, sdyn, 0);

    for (int ko = 0; ko < NKO; ++ko) {
        const uint32_t sb = sdyn + st * STAGE_B;
        #pragma unroll
        for (int kk = 0; kk < 8; ++kk) {
            const int cur = kk & 1;
            if (kk < 7) LOAD_FRAGS(cur ^ 1, sb, kk + 1);
            DO_MMAS(cur);
        }
        if (lane == 0) MBARRIER_ARRIVE(sEmpty + st * 8);
        if (++st == STAGES) { st = 0; ph ^= 1; }
        if (ko + 1 < NKO) {
            MBARRIER_WAIT_PARITY(sFull + st * 8, ph);
            LOAD_FRAGS(0, sdyn + st * STAGE_B, 0);
        }
    }

    // wait for s (long since done in the common case)
    {
        volatile int* f = (volatile int*)&g_s_flag[mb];
        while (*f == 0) {}
        __threadfence();
    }

    // epilogue: y = xhi * softplus(acc + b1) * s   (x read as fp16 from tiles)
    const int kt_e   = (cbase + warp_n * 32) >> 6;
    const int colb   = (cbase + warp_n * 32) & 63;   // 0 or 32
    const char* xt = (const char*)(g_xhi + ((size_t)(mb * 16 + kt_e)) * 1024);

    #pragma unroll
    for (int i = 0; i < 2; ++i) {
        const int row0 = warp_m * 32 + i * 16 + (lane >> 2);
        const int row1 = row0 + 8;
        const int r0 = rbase + row0;
        const int r1 = rbase + row1;
        const float s0 = g_s[r0], s1 = g_s[r1];
        #pragma unroll
        for (int j = 0; j < 4; ++j) {
            const int ci = colb + j * 8 + (lane & 3) * 2;
            const int c  = cbase + warp_n * 32 + j * 8 + (lane & 3) * 2;
            uint32_t off0 = (uint32_t)(row0 * 128 + ci * 2);
            uint32_t off1 = (uint32_t)(row1 * 128 + ci * 2);
            off0 ^= ((off0 >> 3) & 0x70);
            off1 ^= ((off1 >> 3) & 0x70);
            __half2 xh0 = *reinterpret_cast<const __half2*>(xt + off0);
            __half2 xh1 = *reinterpret_cast<const __half2*>(xt + off1);
            float2 bv = *reinterpret_cast<const float2*>(b1 + c);
            float2 o0, o1;
            o0.x = __half2float(xh0.x) * softplusf(acc[i][j][0] + bv.x) * s0;
            o0.y = __half2float(xh0.y) * softplusf(acc[i][j][1] + bv.y) * s0;
            o1.x = __half2float(xh1.x) * softplusf(acc[i][j][2] + bv.x) * s1;
            o1.y = __half2float(xh1.y) * softplusf(acc[i][j][3] + bv.y) * s1;
            *reinterpret_cast<float2*>(y + (size_t)r0 * DDIM + c) = o0;
            *reinterpret_cast<float2*>(y + (size_t)r1 * DDIM + c) = o1;
        }
    }
}

// ---------------------------------------------------------------------------
extern "C" void kernel_launch(void* const* d_in, const int* in_sizes, int n_in,
                              void* d_out, int out_size)
{
    const float* x  = (const float*)d_in[0];
    const float* W1 = (const float*)d_in[1];
    const float* b1 = (const float*)d_in[2];
    const float* W2 = (const float*)d_in[3];
    const float* b2 = (const float*)d_in[4];
    const float* W3 = (const float*)d_in[5];
    const float* b3 = (const float*)d_in[6];
    // d_in[7] = A is mathematically dead (multiplies zero-initialized h).
    float* y = (float*)d_out;

    cudaFuncSetAttribute(gemm_kernel,
                         cudaFuncAttributeMaxDynamicSharedMemorySize, GEMM_SMEM);

    prep_kernel<<<656, 256>>>(x, W1, W2, W3);

    dim3 grid(9, TOKENS / 128);   // x=0: s-CTAs; x=1..8: GEMM
    gemm_kernel<<<grid, 544, GEMM_SMEM>>>(b1, b2, b3, y);
}